// round 6
// baseline (speedup 1.0000x reference)
#include <cuda_runtime.h>
#include <math.h>

#define BB 2
#define LL 256
#define NH 8
#define DQ 64
#define DM 512

// ---------------- scratch (no allocation allowed) ----------------
__device__ float  g_q[BB*NH*LL*DQ];
__device__ float  g_k[BB*NH*LL*DQ];
__device__ float  g_v[BB*NH*LL*DQ];
__device__ float  g_attn[BB*NH*LL*LL];
__device__ float2 g_u[BB*NH*LL*DQ];
__device__ float  g_rnn[BB*LL*DM];

// ---------------- 512x512x512 SGEMM: Out = X@W + bias ----------------
// mode 0/1/2: write remapped (b,h,l,d) into g_q/g_k/g_v.
// mode 3: X is IGNORED; reads g_rnn (device symbol) and writes plain to OutParam.
__global__ __launch_bounds__(256) void sgemm512(
    const float* __restrict__ X, const float* __restrict__ W,
    const float* __restrict__ bias, float* __restrict__ OutParam, int mode)
{
    __shared__ float As[16][64];
    __shared__ float Bs[16][64];
    const float* Xp = (mode == 3) ? g_rnn : X;   // device-symbol resolved on device
    const int tid = threadIdx.x;
    const int tx = tid & 15, ty = tid >> 4;
    const int row0 = blockIdx.x * 64, col0 = blockIdx.y * 64;
    float acc[4][4] = {};
    for (int k0 = 0; k0 < 512; k0 += 16) {
        {
            int m  = tid >> 2;
            int kk = (tid & 3) * 4;
            float4 av = *(const float4*)&Xp[(row0 + m) * 512 + k0 + kk];
            As[kk+0][m] = av.x; As[kk+1][m] = av.y; As[kk+2][m] = av.z; As[kk+3][m] = av.w;
            int kr = tid >> 4;
            int nn = (tid & 15) * 4;
            *(float4*)&Bs[kr][nn] = *(const float4*)&W[(k0 + kr) * 512 + col0 + nn];
        }
        __syncthreads();
        #pragma unroll
        for (int k = 0; k < 16; ++k) {
            float4 a4 = *(const float4*)&As[k][ty * 4];
            float4 b4 = *(const float4*)&Bs[k][tx * 4];
            float a[4] = {a4.x, a4.y, a4.z, a4.w};
            float b[4] = {b4.x, b4.y, b4.z, b4.w};
            #pragma unroll
            for (int i = 0; i < 4; ++i)
                #pragma unroll
                for (int j = 0; j < 4; ++j)
                    acc[i][j] = fmaf(a[i], b[j], acc[i][j]);
        }
        __syncthreads();
    }
    float* Out = OutParam;
    if (mode == 0) Out = g_q; else if (mode == 1) Out = g_k; else if (mode == 2) Out = g_v;
    #pragma unroll
    for (int i = 0; i < 4; ++i) {
        int m = row0 + ty * 4 + i;
        #pragma unroll
        for (int j = 0; j < 4; ++j) {
            int n = col0 + tx * 4 + j;
            float val = acc[i][j] + bias[n];
            if (mode < 3) {
                int b = m >> 8, l = m & 255, h = n >> 6, d = n & 63;
                Out[(((b * NH + h) << 8) + l) * DQ + d] = val;
            } else {
                Out[m * 512 + n] = val;
            }
        }
    }
}

// ---------------- u = v @ (Win_re + i Win_im), per head ----------------
// grid (16 bh, 8 rowblocks of 32), 256 threads
__global__ __launch_bounds__(256) void u_kernel(
    const float* __restrict__ Wre, const float* __restrict__ Wim)
{
    __shared__ float Vs[32][64];
    __shared__ float Wr[64][64];
    __shared__ float Wi[64][64];
    const int bh = blockIdx.x;
    const int rb = blockIdx.y;
    const int h  = bh & 7;
    const int tid = threadIdx.x;
    {
        const float4* vsrc = (const float4*)&g_v[(bh * LL + rb * 32) * DQ];
        float4* vdst = (float4*)&Vs[0][0];
        vdst[tid]       = vsrc[tid];
        vdst[tid + 256] = vsrc[tid + 256];
        const float4* wr = (const float4*)&Wre[h * 4096];
        const float4* wi = (const float4*)&Wim[h * 4096];
        float4* wrd = (float4*)&Wr[0][0];
        float4* wid = (float4*)&Wi[0][0];
        #pragma unroll
        for (int i = 0; i < 4; ++i) {
            wrd[tid + 256 * i] = wr[tid + 256 * i];
            wid[tid + 256 * i] = wi[tid + 256 * i];
        }
    }
    __syncthreads();
    const int tx = tid & 15, ty = tid >> 4;
    float ar[2][4] = {}, ai[2][4] = {};
    #pragma unroll 8
    for (int d = 0; d < 64; ++d) {
        float a0 = Vs[ty * 2 + 0][d];
        float a1 = Vs[ty * 2 + 1][d];
        float4 wr4 = *(const float4*)&Wr[d][tx * 4];
        float4 wi4 = *(const float4*)&Wi[d][tx * 4];
        float wrv[4] = {wr4.x, wr4.y, wr4.z, wr4.w};
        float wiv[4] = {wi4.x, wi4.y, wi4.z, wi4.w};
        #pragma unroll
        for (int j = 0; j < 4; ++j) {
            ar[0][j] = fmaf(a0, wrv[j], ar[0][j]);
            ai[0][j] = fmaf(a0, wiv[j], ai[0][j]);
            ar[1][j] = fmaf(a1, wrv[j], ar[1][j]);
            ai[1][j] = fmaf(a1, wiv[j], ai[1][j]);
        }
    }
    #pragma unroll
    for (int i = 0; i < 2; ++i) {
        int t = rb * 32 + ty * 2 + i;
        #pragma unroll
        for (int j = 0; j < 4; ++j) {
            int e = tx * 4 + j;
            g_u[(bh * LL + t) * DQ + e] = make_float2(ar[i][j], ai[i][j]);
        }
    }
}

// ---------------- logits = q@k^T/8 - mask ----------------
// grid (4 qtiles, 4 ttiles, 16 bh)
__global__ __launch_bounds__(256) void logits_kernel(const float* __restrict__ mask)
{
    __shared__ float Qs[64][65];
    __shared__ float Ks[64][65];
    const int q0 = blockIdx.x * 64, t0 = blockIdx.y * 64, bh = blockIdx.z;
    const int b = bh >> 3;
    const int tid = threadIdx.x;
    {
        const float* qsrc = &g_q[(bh * LL + q0) * DQ];
        const float* ksrc = &g_k[(bh * LL + t0) * DQ];
        #pragma unroll
        for (int i = 0; i < 4; ++i) {
            int idx = tid + 256 * i;          // float4 index 0..1023
            int r = idx >> 4;
            int c = (idx & 15) * 4;
            float4 v = *(const float4*)&qsrc[r * 64 + c];
            Qs[r][c] = v.x; Qs[r][c+1] = v.y; Qs[r][c+2] = v.z; Qs[r][c+3] = v.w;
            float4 w = *(const float4*)&ksrc[r * 64 + c];
            Ks[r][c] = w.x; Ks[r][c+1] = w.y; Ks[r][c+2] = w.z; Ks[r][c+3] = w.w;
        }
    }
    __syncthreads();
    const int tx = tid & 15, ty = tid >> 4;
    float acc[4][4] = {};
    #pragma unroll 8
    for (int d = 0; d < 64; ++d) {
        float a[4], bb[4];
        #pragma unroll
        for (int i = 0; i < 4; ++i) a[i]  = Qs[ty * 4 + i][d];
        #pragma unroll
        for (int j = 0; j < 4; ++j) bb[j] = Ks[tx * 4 + j][d];
        #pragma unroll
        for (int i = 0; i < 4; ++i)
            #pragma unroll
            for (int j = 0; j < 4; ++j)
                acc[i][j] = fmaf(a[i], bb[j], acc[i][j]);
    }
    const float NEG_INF = -__int_as_float(0x7f800000);
    #pragma unroll
    for (int i = 0; i < 4; ++i) {
        int q = q0 + ty * 4 + i;
        #pragma unroll
        for (int j = 0; j < 4; ++j) {
            int t = t0 + tx * 4 + j;
            float v = acc[i][j] * 0.125f;
            float mval = mask[b * LL * LL + q * LL + t];
            v = (mval == 1.0f) ? NEG_INF : v - mval;
            g_attn[(bh * LL + q) * LL + t] = v;
        }
    }
}

// ---------------- row softmax, one warp per (b,h,q) row ----------------
__global__ __launch_bounds__(256) void softmax_kernel(float* __restrict__ attn_out)
{
    const int w = (blockIdx.x * blockDim.x + threadIdx.x) >> 5;  // 0..4095
    const int lane = threadIdx.x & 31;
    float* row = &g_attn[w * LL];
    float x[8];
    float mx = -__int_as_float(0x7f800000);
    #pragma unroll
    for (int j = 0; j < 8; ++j) { x[j] = row[lane + 32 * j]; mx = fmaxf(mx, x[j]); }
    #pragma unroll
    for (int off = 16; off > 0; off >>= 1) mx = fmaxf(mx, __shfl_xor_sync(0xffffffffu, mx, off));
    float s = 0.0f;
    #pragma unroll
    for (int j = 0; j < 8; ++j) { x[j] = __expf(x[j] - mx); s += x[j]; }
    #pragma unroll
    for (int off = 16; off > 0; off >>= 1) s += __shfl_xor_sync(0xffffffffu, s, off);
    float inv = 1.0f / s;
    #pragma unroll
    for (int j = 0; j < 8; ++j) {
        float v = x[j] * inv;
        row[lane + 32 * j] = v;
        if (attn_out) attn_out[w * LL + lane + 32 * j] = v;
    }
}

// ---------------- sequential EUNN scan: one warp per (b,h,q) chain ----------------
__global__ __launch_bounds__(256) void rnn_kernel(
    const float* __restrict__ theta, const float* __restrict__ phi,
    const float* __restrict__ rbias)
{
    const int w = (blockIdx.x * blockDim.x + threadIdx.x) >> 5;  // 0..4095
    const int lane = threadIdx.x & 31;
    const int bh = w >> 8;
    const int q  = w & 255;
    const int h  = bh & 7;

    float c0, s0, cp0, sp0, c1, s1, cp1, sp1;
    sincosf(theta[(h * 2 + 0) * 32 + lane], &s0, &c0);
    sincosf(theta[(h * 2 + 1) * 32 + lane], &s1, &c1);
    sincosf(phi[(h * 2 + 0) * 32 + lane], &sp0, &cp0);
    sincosf(phi[(h * 2 + 1) * 32 + lane], &sp1, &cp1);
    const float bb0 = rbias[h * 64 + 2 * lane];
    const float bb1 = rbias[h * 64 + 2 * lane + 1];

    const float* arow = &g_attn[(bh * LL + q) * LL];
    const float4* ub  = (const float4*)&g_u[bh * LL * DQ];  // [t*32+lane] -> (u[e0], u[e1])

    float h0r = 0.f, h0i = 0.f, h1r = 0.f, h1i = 0.f;
    const unsigned FULL = 0xffffffffu;

    for (int t = 0; t < LL; ++t) {
        float a = arow[t];                 // warp-uniform broadcast load
        float4 u4 = ub[t * 32 + lane];
        // --- unitary layer 0: pair (2*lane, 2*lane+1), lane-local ---
        {
            float pbr = cp0 * h1r - sp0 * h1i;     // e^{i phi} * b
            float pbi = cp0 * h1i + sp0 * h1r;
            float nar = c0 * h0r - s0 * pbr;
            float nai = c0 * h0i - s0 * pbi;
            float par = cp0 * h0r + sp0 * h0i;     // e^{-i phi} * a
            float pai = cp0 * h0i - sp0 * h0r;
            float nbr = s0 * par + c0 * h1r;
            float nbi = s0 * pai + c0 * h1i;
            h0r = nar; h0i = nai; h1r = nbr; h1i = nbi;
        }
        // --- unitary layer 1: pair (2*lane+1, 2*lane+2 mod 64), cross-lane ---
        {
            float b2r = __shfl_sync(FULL, h0r, (lane + 1) & 31);
            float b2i = __shfl_sync(FULL, h0i, (lane + 1) & 31);
            float pbr = cp1 * b2r - sp1 * b2i;
            float pbi = cp1 * b2i + sp1 * b2r;
            float nar = c1 * h1r - s1 * pbr;       // new element 2*lane+1
            float nai = c1 * h1i - s1 * pbi;
            float par = cp1 * h1r + sp1 * h1i;
            float pai = cp1 * h1i - sp1 * h1r;
            float nbr = s1 * par + c1 * b2r;       // new element 2*lane+2 (lane+1's h0)
            float nbi = s1 * pai + c1 * b2i;
            h1r = nar; h1i = nai;
            h0r = __shfl_sync(FULL, nbr, (lane + 31) & 31);
            h0i = __shfl_sync(FULL, nbi, (lane + 31) & 31);
        }
        // --- + wx = a * u ---
        h0r = fmaf(a, u4.x, h0r); h0i = fmaf(a, u4.y, h0i);
        h1r = fmaf(a, u4.z, h1r); h1i = fmaf(a, u4.w, h1i);
        // --- modrelu ---
        {
            float m0 = sqrtf(h0r * h0r + h0i * h0i);
            float sc0 = fmaxf(m0 + bb0, 0.0f) / (m0 + 1e-5f);
            h0r *= sc0; h0i *= sc0;
            float m1 = sqrtf(h1r * h1r + h1i * h1i);
            float sc1 = fmaxf(m1 + bb1, 0.0f) / (m1 + 1e-5f);
            h1r *= sc1; h1i *= sc1;
        }
    }
    const int b = bh >> 3;
    float* dst = &g_rnn[(b * LL + q) * DM + h * DQ];
    dst[2 * lane]     = h0r;
    dst[2 * lane + 1] = h1r;
}

// ---------------- launch ----------------
extern "C" void kernel_launch(void* const* d_in, const int* in_sizes, int n_in,
                              void* d_out, int out_size)
{
    const float* x_q    = (const float*)d_in[0];
    const float* x_k    = (const float*)d_in[1];
    const float* x_v    = (const float*)d_in[2];
    const float* maskp  = (const float*)d_in[3];
    const float* Wq     = (const float*)d_in[4];
    const float* bq     = (const float*)d_in[5];
    const float* Wk     = (const float*)d_in[6];
    const float* bk     = (const float*)d_in[7];
    const float* Wv     = (const float*)d_in[8];
    const float* bv     = (const float*)d_in[9];
    const float* Wo     = (const float*)d_in[10];
    const float* bo     = (const float*)d_in[11];
    const float* theta  = (const float*)d_in[12];
    const float* phi    = (const float*)d_in[13];
    const float* Win_re = (const float*)d_in[14];
    const float* Win_im = (const float*)d_in[15];
    const float* rbias  = (const float*)d_in[16];

    float* out = (float*)d_out;
    const int OUT_ELEMS  = BB * LL * DM;          // 262144
    const int ATTN_ELEMS = BB * NH * LL * LL;     // 1048576
    float* attn_out = (out_size >= OUT_ELEMS + ATTN_ELEMS) ? (out + OUT_ELEMS) : nullptr;

    dim3 g88(8, 8);
    sgemm512<<<g88, 256>>>(x_q, Wq, bq, nullptr, 0);
    sgemm512<<<g88, 256>>>(x_k, Wk, bk, nullptr, 1);
    sgemm512<<<g88, 256>>>(x_v, Wv, bv, nullptr, 2);

    u_kernel<<<dim3(BB * NH, 8), 256>>>(Win_re, Win_im);

    logits_kernel<<<dim3(4, 4, BB * NH), 256>>>(maskp);

    softmax_kernel<<<512, 256>>>(attn_out);

    rnn_kernel<<<512, 256>>>(theta, phi, rbias);

    // mode 3: reads g_rnn internally (device symbol must not be passed from host)
    sgemm512<<<g88, 256>>>(nullptr, Wo, bo, out, 3);
}

// round 7
// speedup vs baseline: 1.5278x; 1.5278x over previous
#include <cuda_runtime.h>
#include <math.h>

#define BB 2
#define LL 256
#define NH 8
#define DQ 64
#define DM 512

// ---------------- scratch (no allocation allowed) ----------------
__device__ float  g_q[BB*NH*LL*DQ];
__device__ float  g_k[BB*NH*LL*DQ];
__device__ float  g_v[BB*NH*LL*DQ];
__device__ float  g_attn[BB*NH*LL*LL];     // raw logits (softmax happens in rnn)
__device__ float2 g_u[BB*NH*LL*DQ];
__device__ float  g_rnn[BB*LL*DM];

// ---------------- fused QKV 512x512x512 SGEMM, z selects projection ----------------
// Writes remapped (b,h,l,d) into g_q/g_k/g_v.
__global__ __launch_bounds__(256) void qkv_gemm(
    const float* __restrict__ xq, const float* __restrict__ xk, const float* __restrict__ xv,
    const float* __restrict__ Wq, const float* __restrict__ Wk, const float* __restrict__ Wv,
    const float* __restrict__ bq, const float* __restrict__ bk, const float* __restrict__ bv)
{
    __shared__ float As[16][64];
    __shared__ float Bs[16][64];
    const int z = blockIdx.z;
    const float* X    = (z == 0) ? xq : (z == 1) ? xk : xv;
    const float* W    = (z == 0) ? Wq : (z == 1) ? Wk : Wv;
    const float* bias = (z == 0) ? bq : (z == 1) ? bk : bv;
    float* Out        = (z == 0) ? g_q : (z == 1) ? g_k : g_v;

    const int tid = threadIdx.x;
    const int tx = tid & 15, ty = tid >> 4;
    const int row0 = blockIdx.x * 64, col0 = blockIdx.y * 64;
    float acc[4][4] = {};
    for (int k0 = 0; k0 < 512; k0 += 16) {
        {
            int m  = tid >> 2;
            int kk = (tid & 3) * 4;
            float4 av = *(const float4*)&X[(row0 + m) * 512 + k0 + kk];
            As[kk+0][m] = av.x; As[kk+1][m] = av.y; As[kk+2][m] = av.z; As[kk+3][m] = av.w;
            int kr = tid >> 4;
            int nn = (tid & 15) * 4;
            *(float4*)&Bs[kr][nn] = *(const float4*)&W[(k0 + kr) * 512 + col0 + nn];
        }
        __syncthreads();
        #pragma unroll
        for (int k = 0; k < 16; ++k) {
            float4 a4 = *(const float4*)&As[k][ty * 4];
            float4 b4 = *(const float4*)&Bs[k][tx * 4];
            float a[4] = {a4.x, a4.y, a4.z, a4.w};
            float b[4] = {b4.x, b4.y, b4.z, b4.w};
            #pragma unroll
            for (int i = 0; i < 4; ++i)
                #pragma unroll
                for (int j = 0; j < 4; ++j)
                    acc[i][j] = fmaf(a[i], b[j], acc[i][j]);
        }
        __syncthreads();
    }
    #pragma unroll
    for (int i = 0; i < 4; ++i) {
        int m = row0 + ty * 4 + i;
        #pragma unroll
        for (int j = 0; j < 4; ++j) {
            int n = col0 + tx * 4 + j;
            float val = acc[i][j] + bias[n];
            int b = m >> 8, l = m & 255, h = n >> 6, d = n & 63;
            Out[(((b * NH + h) << 8) + l) * DQ + d] = val;
        }
    }
}

// ---------------- output GEMM: out = g_rnn @ Wo + bo ----------------
__global__ __launch_bounds__(256) void out_gemm(
    const float* __restrict__ W, const float* __restrict__ bias, float* __restrict__ Out)
{
    __shared__ float As[16][64];
    __shared__ float Bs[16][64];
    const float* X = g_rnn;
    const int tid = threadIdx.x;
    const int tx = tid & 15, ty = tid >> 4;
    const int row0 = blockIdx.x * 64, col0 = blockIdx.y * 64;
    float acc[4][4] = {};
    for (int k0 = 0; k0 < 512; k0 += 16) {
        {
            int m  = tid >> 2;
            int kk = (tid & 3) * 4;
            float4 av = *(const float4*)&X[(row0 + m) * 512 + k0 + kk];
            As[kk+0][m] = av.x; As[kk+1][m] = av.y; As[kk+2][m] = av.z; As[kk+3][m] = av.w;
            int kr = tid >> 4;
            int nn = (tid & 15) * 4;
            *(float4*)&Bs[kr][nn] = *(const float4*)&W[(k0 + kr) * 512 + col0 + nn];
        }
        __syncthreads();
        #pragma unroll
        for (int k = 0; k < 16; ++k) {
            float4 a4 = *(const float4*)&As[k][ty * 4];
            float4 b4 = *(const float4*)&Bs[k][tx * 4];
            float a[4] = {a4.x, a4.y, a4.z, a4.w};
            float b[4] = {b4.x, b4.y, b4.z, b4.w};
            #pragma unroll
            for (int i = 0; i < 4; ++i)
                #pragma unroll
                for (int j = 0; j < 4; ++j)
                    acc[i][j] = fmaf(a[i], b[j], acc[i][j]);
        }
        __syncthreads();
    }
    #pragma unroll
    for (int i = 0; i < 4; ++i) {
        int m = row0 + ty * 4 + i;
        #pragma unroll
        for (int j = 0; j < 4; ++j) {
            int n = col0 + tx * 4 + j;
            Out[m * 512 + n] = acc[i][j] + bias[n];
        }
    }
}

// ---------------- u = v @ (Win_re + i Win_im), per head ----------------
__global__ __launch_bounds__(256) void u_kernel(
    const float* __restrict__ Wre, const float* __restrict__ Wim)
{
    __shared__ float Vs[32][64];
    __shared__ float Wr[64][64];
    __shared__ float Wi[64][64];
    const int bh = blockIdx.x;
    const int rb = blockIdx.y;
    const int h  = bh & 7;
    const int tid = threadIdx.x;
    {
        const float4* vsrc = (const float4*)&g_v[(bh * LL + rb * 32) * DQ];
        float4* vdst = (float4*)&Vs[0][0];
        vdst[tid]       = vsrc[tid];
        vdst[tid + 256] = vsrc[tid + 256];
        const float4* wr = (const float4*)&Wre[h * 4096];
        const float4* wi = (const float4*)&Wim[h * 4096];
        float4* wrd = (float4*)&Wr[0][0];
        float4* wid = (float4*)&Wi[0][0];
        #pragma unroll
        for (int i = 0; i < 4; ++i) {
            wrd[tid + 256 * i] = wr[tid + 256 * i];
            wid[tid + 256 * i] = wi[tid + 256 * i];
        }
    }
    __syncthreads();
    const int tx = tid & 15, ty = tid >> 4;
    float ar[2][4] = {}, ai[2][4] = {};
    #pragma unroll 8
    for (int d = 0; d < 64; ++d) {
        float a0 = Vs[ty * 2 + 0][d];
        float a1 = Vs[ty * 2 + 1][d];
        float4 wr4 = *(const float4*)&Wr[d][tx * 4];
        float4 wi4 = *(const float4*)&Wi[d][tx * 4];
        float wrv[4] = {wr4.x, wr4.y, wr4.z, wr4.w};
        float wiv[4] = {wi4.x, wi4.y, wi4.z, wi4.w};
        #pragma unroll
        for (int j = 0; j < 4; ++j) {
            ar[0][j] = fmaf(a0, wrv[j], ar[0][j]);
            ai[0][j] = fmaf(a0, wiv[j], ai[0][j]);
            ar[1][j] = fmaf(a1, wrv[j], ar[1][j]);
            ai[1][j] = fmaf(a1, wiv[j], ai[1][j]);
        }
    }
    #pragma unroll
    for (int i = 0; i < 2; ++i) {
        int t = rb * 32 + ty * 2 + i;
        #pragma unroll
        for (int j = 0; j < 4; ++j) {
            int e = tx * 4 + j;
            g_u[(bh * LL + t) * DQ + e] = make_float2(ar[i][j], ai[i][j]);
        }
    }
}

// ---------------- logits = q@k^T/8 - mask (raw, pre-softmax) ----------------
__global__ __launch_bounds__(256) void logits_kernel(const float* __restrict__ mask)
{
    __shared__ float Qs[64][65];
    __shared__ float Ks[64][65];
    const int q0 = blockIdx.x * 64, t0 = blockIdx.y * 64, bh = blockIdx.z;
    const int b = bh >> 3;
    const int tid = threadIdx.x;
    {
        const float* qsrc = &g_q[(bh * LL + q0) * DQ];
        const float* ksrc = &g_k[(bh * LL + t0) * DQ];
        #pragma unroll
        for (int i = 0; i < 4; ++i) {
            int idx = tid + 256 * i;
            int r = idx >> 4;
            int c = (idx & 15) * 4;
            float4 v = *(const float4*)&qsrc[r * 64 + c];
            Qs[r][c] = v.x; Qs[r][c+1] = v.y; Qs[r][c+2] = v.z; Qs[r][c+3] = v.w;
            float4 w = *(const float4*)&ksrc[r * 64 + c];
            Ks[r][c] = w.x; Ks[r][c+1] = w.y; Ks[r][c+2] = w.z; Ks[r][c+3] = w.w;
        }
    }
    __syncthreads();
    const int tx = tid & 15, ty = tid >> 4;
    float acc[4][4] = {};
    #pragma unroll 8
    for (int d = 0; d < 64; ++d) {
        float a[4], bb[4];
        #pragma unroll
        for (int i = 0; i < 4; ++i) a[i]  = Qs[ty * 4 + i][d];
        #pragma unroll
        for (int j = 0; j < 4; ++j) bb[j] = Ks[tx * 4 + j][d];
        #pragma unroll
        for (int i = 0; i < 4; ++i)
            #pragma unroll
            for (int j = 0; j < 4; ++j)
                acc[i][j] = fmaf(a[i], bb[j], acc[i][j]);
    }
    const float NEG_INF = -__int_as_float(0x7f800000);
    #pragma unroll
    for (int i = 0; i < 4; ++i) {
        int q = q0 + ty * 4 + i;
        #pragma unroll
        for (int j = 0; j < 4; ++j) {
            int t = t0 + tx * 4 + j;
            float v = acc[i][j] * 0.125f;
            float mval = mask[b * LL * LL + q * LL + t];
            v = (mval == 1.0f) ? NEG_INF : v - mval;
            g_attn[(bh * LL + q) * LL + t] = v;
        }
    }
}

// ---------------- fused softmax + EUNN scan: one warp per (b,h,q) chain ----------------
__global__ __launch_bounds__(256) void rnn_kernel(
    const float* __restrict__ theta, const float* __restrict__ phi,
    const float* __restrict__ rbias, float* __restrict__ attn_out)
{
    const int w = (blockIdx.x * blockDim.x + threadIdx.x) >> 5;  // 0..4095
    const int lane = threadIdx.x & 31;
    const int bh = w >> 8;
    const int q  = w & 255;
    const int h  = bh & 7;
    const unsigned FULL = 0xffffffffu;

    // ---- rotation coefficients (loop-invariant) ----
    float c0, s0, cp0, sp0, c1, s1, cp1, sp1;
    sincosf(theta[(h * 2 + 0) * 32 + lane], &s0, &c0);
    sincosf(theta[(h * 2 + 1) * 32 + lane], &s1, &c1);
    sincosf(phi[(h * 2 + 0) * 32 + lane], &sp0, &cp0);
    sincosf(phi[(h * 2 + 1) * 32 + lane], &sp1, &cp1);
    // lane-1 copies of layer-1 coefficients (for computing this lane's new h0)
    const int lm = (lane + 31) & 31;
    const float c1m  = __shfl_sync(FULL, c1,  lm);
    const float s1m  = __shfl_sync(FULL, s1,  lm);
    const float cp1m = __shfl_sync(FULL, cp1, lm);
    const float sp1m = __shfl_sync(FULL, sp1, lm);
    const float bb0 = rbias[h * 64 + 2 * lane];
    const float bb1 = rbias[h * 64 + 2 * lane + 1];

    // ---- in-register softmax of this row ----
    const float* row = &g_attn[(bh * LL + q) * LL];
    float x[8];
    float mx = -__int_as_float(0x7f800000);
    #pragma unroll
    for (int j = 0; j < 8; ++j) { x[j] = row[lane + 32 * j]; mx = fmaxf(mx, x[j]); }
    #pragma unroll
    for (int off = 16; off > 0; off >>= 1) mx = fmaxf(mx, __shfl_xor_sync(FULL, mx, off));
    float s = 0.0f;
    #pragma unroll
    for (int j = 0; j < 8; ++j) { x[j] = __expf(x[j] - mx); s += x[j]; }
    #pragma unroll
    for (int off = 16; off > 0; off >>= 1) s += __shfl_xor_sync(FULL, s, off);
    float inv = 1.0f / s;
    #pragma unroll
    for (int j = 0; j < 8; ++j) x[j] *= inv;
    if (attn_out) {
        float* ao = &attn_out[(bh * LL + q) * LL];
        #pragma unroll
        for (int j = 0; j < 8; ++j) ao[lane + 32 * j] = x[j];
    }

    // ---- sequential scan ----
    const float4* ub = (const float4*)&g_u[bh * LL * DQ];  // [t*32+lane]
    float h0r = 0.f, h0i = 0.f, h1r = 0.f, h1i = 0.f;
    float4 u4 = ub[lane];                                   // prefetch t=0

    for (int chunk = 0; chunk < 8; ++chunk) {
        float xa = x[chunk];
        #pragma unroll 4
        for (int tt = 0; tt < 32; ++tt) {
            const int t = chunk * 32 + tt;
            float a = __shfl_sync(FULL, xa, tt);
            float4 u4n = ub[(((t + 1) & 255) << 5) + lane];  // prefetch next
            // --- layer 0: pair (2l, 2l+1), lane-local ---
            {
                float pbr = cp0 * h1r - sp0 * h1i;      // e^{i phi0} * h1
                float pbi = cp0 * h1i + sp0 * h1r;
                float nar = c0 * h0r - s0 * pbr;
                float nai = c0 * h0i - s0 * pbi;
                float par = cp0 * h0r + sp0 * h0i;      // e^{-i phi0} * h0
                float pai = cp0 * h0i - sp0 * h0r;
                float nbr = fmaf(s0, par, c0 * h1r);
                float nbi = fmaf(s0, pai, c0 * h1i);
                h0r = nar; h0i = nai; h1r = nbr; h1i = nbi;
            }
            // --- layer 1: parallel shuffles on OLD (layer-0) state ---
            {
                float h0pr = __shfl_sync(FULL, h0r, (lane + 1) & 31);  // h0 of lane+1
                float h0pi = __shfl_sync(FULL, h0i, (lane + 1) & 31);
                float h1mr = __shfl_sync(FULL, h1r, lm);               // h1 of lane-1
                float h1mi = __shfl_sync(FULL, h1i, lm);
                // new h1[l] = c1*h1 - s1*(e^{i phi1} * h0[l+1])
                float pbr = cp1 * h0pr - sp1 * h0pi;
                float pbi = cp1 * h0pi + sp1 * h0pr;
                float nh1r = c1 * h1r - s1 * pbr;
                float nh1i = c1 * h1i - s1 * pbi;
                // new h0[l] = s1m*(e^{-i phi1m} * h1[l-1]) + c1m*h0[l]
                float qr = cp1m * h1mr + sp1m * h1mi;
                float qi = cp1m * h1mi - sp1m * h1mr;
                h0r = fmaf(s1m, qr, c1m * h0r);
                h0i = fmaf(s1m, qi, c1m * h0i);
                h1r = nh1r; h1i = nh1i;
            }
            // --- + a * u ---
            h0r = fmaf(a, u4.x, h0r); h0i = fmaf(a, u4.y, h0i);
            h1r = fmaf(a, u4.z, h1r); h1i = fmaf(a, u4.w, h1i);
            u4 = u4n;
            // --- modrelu (fast rsqrt/rcp path) ---
            {
                float m2_0 = fmaf(h0r, h0r, h0i * h0i);
                float rs0  = rsqrtf(fmaxf(m2_0, 1e-36f));
                float m0   = m2_0 * rs0;
                float sc0  = __fdividef(fmaxf(m0 + bb0, 0.0f), m0 + 1e-5f);
                h0r *= sc0; h0i *= sc0;
                float m2_1 = fmaf(h1r, h1r, h1i * h1i);
                float rs1  = rsqrtf(fmaxf(m2_1, 1e-36f));
                float m1   = m2_1 * rs1;
                float sc1  = __fdividef(fmaxf(m1 + bb1, 0.0f), m1 + 1e-5f);
                h1r *= sc1; h1i *= sc1;
            }
        }
    }
    const int b = bh >> 3;
    float* dst = &g_rnn[(b * LL + q) * DM + h * DQ];
    dst[2 * lane]     = h0r;
    dst[2 * lane + 1] = h1r;
}

// ---------------- launch ----------------
extern "C" void kernel_launch(void* const* d_in, const int* in_sizes, int n_in,
                              void* d_out, int out_size)
{
    const float* x_q    = (const float*)d_in[0];
    const float* x_k    = (const float*)d_in[1];
    const float* x_v    = (const float*)d_in[2];
    const float* maskp  = (const float*)d_in[3];
    const float* Wq     = (const float*)d_in[4];
    const float* bq     = (const float*)d_in[5];
    const float* Wk     = (const float*)d_in[6];
    const float* bk     = (const float*)d_in[7];
    const float* Wv     = (const float*)d_in[8];
    const float* bv     = (const float*)d_in[9];
    const float* Wo     = (const float*)d_in[10];
    const float* bo     = (const float*)d_in[11];
    const float* theta  = (const float*)d_in[12];
    const float* phi    = (const float*)d_in[13];
    const float* Win_re = (const float*)d_in[14];
    const float* Win_im = (const float*)d_in[15];
    const float* rbias  = (const float*)d_in[16];

    float* out = (float*)d_out;
    const int OUT_ELEMS  = BB * LL * DM;          // 262144
    const int ATTN_ELEMS = BB * NH * LL * LL;     // 1048576
    float* attn_out = (out_size >= OUT_ELEMS + ATTN_ELEMS) ? (out + OUT_ELEMS) : nullptr;

    qkv_gemm<<<dim3(8, 8, 3), 256>>>(x_q, x_k, x_v, Wq, Wk, Wv, bq, bk, bv);

    u_kernel<<<dim3(BB * NH, 8), 256>>>(Win_re, Win_im);

    logits_kernel<<<dim3(4, 4, BB * NH), 256>>>(maskp);

    rnn_kernel<<<512, 256>>>(theta, phi, rbias, attn_out);

    out_gemm<<<dim3(8, 8), 256>>>(Wo, bo, out);
}